// round 11
// baseline (speedup 1.0000x reference)
#include <cuda_runtime.h>
#include <cuda_fp16.h>

#define N_NODES   8192
#define B_BATCH   2
#define D_IN      64
#define D_OUT     32
#define K_ITERS   4
#define C_CH      (K_ITERS * D_OUT)   // 128
#define ALPHA_F   0.1f
#define OMA_F     0.9f
#define BN_EPS_F  1e-5f
#define MAX_NNZ   128
#define NSAMP     (B_BATCH * N_NODES)
#define NBLK      1024                 // 8 rows per block, warp per row
#define GEMM_BLOCKS 1024

// ---------------- device scratch ----------------
__device__ __half2 g_hkA[N_NODES * D_OUT];               // ping [n][f] -> (b0,b1)
__device__ __half2 g_hkB[N_NODES * D_OUT];               // pong
__device__ float2  g_h0 [N_NODES * D_OUT];               // alpha*(x0@W0)
__device__ int4    g_cv4[(size_t)N_NODES * MAX_NNZ / 2]; // {col*32,val}x2
__device__ int     g_cnt[N_NODES];                       // padded to mult of 8
__device__ float   g_y  [(size_t)B_BATCH * N_NODES * C_CH];
__device__ float   g_psum[K_ITERS * NBLK * D_OUT];
__device__ float   g_psq [K_ITERS * NBLK * D_OUT];
__device__ float   g_scale[C_CH];
__device__ float   g_shift[C_CH];
__device__ int     g_bar = 0;                            // barrier arrivals
__device__ int     g_gen = 0;                            // barrier generation

// device-wide sense barrier (all NBLK blocks resident by construction)
__device__ __forceinline__ void grid_sync() {
    __syncthreads();
    if (threadIdx.x == 0) {
        __threadfence();
        const int my = *(volatile int*)&g_gen;
        if (atomicAdd(&g_bar, 1) == NBLK - 1) {
            atomicExch(&g_bar, 0);
            __threadfence();
            atomicAdd(&g_gen, 1);
        } else {
            while (*(volatile int*)&g_gen == my) { }
        }
        __threadfence();
    }
    __syncthreads();
}

// ---------------- 1) fused: projections (blocks < GEMM_BLOCKS) + CSR build ---
// gemm blocks are issue/latency-bound; csr blocks are DRAM-bound. Interleaved
// on the SMs, gemm fills the idle issue slots of the adjacency scan.
__global__ void pre_kernel(const float* __restrict__ x,
                           const float* __restrict__ x0,
                           const float* __restrict__ W,
                           const float* __restrict__ W0,
                           const float* __restrict__ adj) {
    __shared__ float Ws [D_IN * D_OUT];
    __shared__ float W0s[D_IN * D_OUT];
    __shared__ float xa [8][D_IN], xb [8][D_IN];
    __shared__ float x0a[8][D_IN], x0b[8][D_IN];

    if (blockIdx.x < GEMM_BLOCKS) {
        // ---- GEMM: 8 node rows, both batches per thread ----
        const int t = threadIdx.x;
        const int rowBase = blockIdx.x * 8;

        for (int i = t; i < D_IN * D_OUT; i += 256) { Ws[i] = W[i]; W0s[i] = W0[i]; }
        for (int i = t; i < 8 * D_IN; i += 256) {
            const int r = rowBase + (i >> 6);
            const int d = i & 63;
            xa [i >> 6][d] = x [(size_t)r * D_IN + d];
            xb [i >> 6][d] = x [(size_t)(N_NODES + r) * D_IN + d];
            x0a[i >> 6][d] = x0[(size_t)r * D_IN + d];
            x0b[i >> 6][d] = x0[(size_t)(N_NODES + r) * D_IN + d];
        }
        __syncthreads();

        const int rr = t >> 5;
        const int f  = t & 31;
        const int row = rowBase + rr;
        float ha = 0.f, hb = 0.f, za = 0.f, zb = 0.f;
#pragma unroll
        for (int d = 0; d < D_IN; ++d) {
            const float w  = Ws [d * D_OUT + f];
            const float w0 = W0s[d * D_OUT + f];
            ha = fmaf(xa [rr][d], w,  ha);
            hb = fmaf(xb [rr][d], w,  hb);
            za = fmaf(x0a[rr][d], w0, za);
            zb = fmaf(x0b[rr][d], w0, zb);
        }
        g_hkA[row * D_OUT + f] = __floats2half2_rn(ha, hb);
        g_h0 [row * D_OUT + f] = make_float2(za * ALPHA_F, zb * ALPHA_F);
    } else {
        // ---- CSR build: warp per adjacency row (col stored * D_OUT) ----
        const int warp = ((blockIdx.x - GEMM_BLOCKS) * 256 + threadIdx.x) >> 5;
        const int lane = threadIdx.x & 31;

        const float4* row = (const float4*)(adj + (size_t)warp * N_NODES);
        int2* out = (int2*)&g_cv4[(size_t)warp * (MAX_NNZ / 2)];
        int base = 0;

        for (int ch = 0; ch < N_NODES / 128; ch += 2) {
            float4 vA = __ldcs(&row[ch * 32 + lane]);
            float4 vB = __ldcs(&row[(ch + 1) * 32 + lane]);
#pragma unroll
            for (int half = 0; half < 2; ++half) {
                const float4 v = half ? vB : vA;
                const bool any = (v.x != 0.f) | (v.y != 0.f) | (v.z != 0.f) | (v.w != 0.f);
                const unsigned am = __ballot_sync(0xffffffffu, any);
                if (am == 0u) continue;                 // uniform branch
                const float e[4] = {v.x, v.y, v.z, v.w};
#pragma unroll
                for (int k = 0; k < 4; ++k) {
                    const bool nz = (e[k] != 0.0f);
                    const unsigned m = __ballot_sync(0xffffffffu, nz);
                    if (nz) {
                        int pos = base + __popc(m & ((1u << lane) - 1u));
                        if (pos < MAX_NNZ)
                            out[pos] = make_int2(((ch + half) * 128 + lane * 4 + k) << 5,
                                                 __float_as_int(e[k] * OMA_F));
                    }
                    base += __popc(m);
                }
            }
        }
        int cnt  = base < MAX_NNZ ? base : MAX_NNZ;
        int cntp = (cnt + 7) & ~7;
        for (int j = cnt + lane; j < cntp; j += 32)
            out[j] = make_int2(0, 0);                    // val = 0 padding
        if (lane == 0) g_cnt[warp] = cntp;
    }
}

// ---------------- 2) persistent: iterates 1-4 + BN + norm + ReLU -------------
__global__ void __launch_bounds__(256, 8)
post_kernel(const float* __restrict__ gamma,
            const float* __restrict__ beta,
            float* __restrict__ out) {
    __shared__ int4  meta[8][MAX_NNZ / 2];     // 8 KB
    __shared__ float shs[8][32];
    __shared__ float shq[8][32];

    const int warp = threadIdx.x >> 5;
    const int lane = threadIdx.x & 31;
    const int r    = blockIdx.x * 8 + warp;

    // stage metadata ONCE for all 4 iterates
    const int4* __restrict__ cv = g_cv4 + (size_t)r * (MAX_NNZ / 2);
    meta[warp][lane]      = __ldg(&cv[lane]);
    meta[warp][lane + 32] = __ldg(&cv[lane + 32]);
    const int nIt = g_cnt[r] >> 2;             // groups of 4 nnz
    const float2 h0 = __ldg(&g_h0[r * D_OUT + lane]);
    __syncwarp();

    for (int k = 0; k < 4; ++k) {
        const __half2* __restrict__ src = (k & 1) ? g_hkB : g_hkA;
        __half2* __restrict__ dst       = (k & 1) ? g_hkA : g_hkB;

        float acc0 = h0.x, acc1 = h0.y;
#pragma unroll 2
        for (int it = 0; it < nIt; ++it) {
            const int4 a = meta[warp][it * 2 + 0];   // uniform LDS.128
            const int4 b = meta[warp][it * 2 + 1];

            const __half2 g0 = __ldg(&src[a.x + lane]);
            const __half2 g1 = __ldg(&src[a.z + lane]);
            const __half2 g2 = __ldg(&src[b.x + lane]);
            const __half2 g3 = __ldg(&src[b.z + lane]);

            float2 f;
            f = __half22float2(g0); acc0 = fmaf(__int_as_float(a.y), f.x, acc0); acc1 = fmaf(__int_as_float(a.y), f.y, acc1);
            f = __half22float2(g1); acc0 = fmaf(__int_as_float(a.w), f.x, acc0); acc1 = fmaf(__int_as_float(a.w), f.y, acc1);
            f = __half22float2(g2); acc0 = fmaf(__int_as_float(b.y), f.x, acc0); acc1 = fmaf(__int_as_float(b.y), f.y, acc1);
            f = __half22float2(g3); acc0 = fmaf(__int_as_float(b.w), f.x, acc0); acc1 = fmaf(__int_as_float(b.w), f.y, acc1);
        }

        if (k < 3)
            dst[r * D_OUT + lane] = __floats2half2_rn(acc0, acc1);
        g_y[(size_t)r * C_CH + k * D_OUT + lane]             = acc0;
        g_y[(size_t)(N_NODES + r) * C_CH + k * D_OUT + lane] = acc1;

        shs[warp][lane] = acc0 + acc1;
        shq[warp][lane] = fmaf(acc0, acc0, acc1 * acc1);
        __syncthreads();
        if (warp == 0) {
            float s = 0.f;
#pragma unroll
            for (int w = 0; w < 8; ++w) s += shs[w][lane];
            g_psum[(k * NBLK + blockIdx.x) * D_OUT + lane] = s;
        }
        if (warp == 1) {
            float q = 0.f;
#pragma unroll
            for (int w = 0; w < 8; ++w) q += shq[w][lane];
            g_psq[(k * NBLK + blockIdx.x) * D_OUT + lane] = q;
        }
        grid_sync();                           // hk + partials visible everywhere
    }

    // ---- BN finalize: block c (c < 128) owns channel c ----
    if (blockIdx.x < C_CH) {
        const int c     = blockIdx.x;
        const int slice = c >> 5;
        const int ln    = c & 31;
        const int t     = threadIdx.x;
        float s = 0.f, q = 0.f;
        for (int j = t; j < NBLK; j += 256) {
            s += g_psum[(slice * NBLK + j) * D_OUT + ln];
            q += g_psq [(slice * NBLK + j) * D_OUT + ln];
        }
        float* fs = &shs[0][0];
        float* fq = &shq[0][0];
        fs[t] = s; fq[t] = q;
        __syncthreads();
        if (t < 128) { fs[t] += fs[t + 128]; fq[t] += fq[t + 128]; }
        __syncthreads();
        if (t < 64)  { fs[t] += fs[t + 64];  fq[t] += fq[t + 64];  }
        __syncthreads();
        if (t < 32) {
            s = fs[t] + fs[t + 32];
            q = fq[t] + fq[t + 32];
#pragma unroll
            for (int off = 16; off > 0; off >>= 1) {
                s += __shfl_down_sync(0xffffffffu, s, off);
                q += __shfl_down_sync(0xffffffffu, q, off);
            }
            if (t == 0) {
                const float inv  = 1.0f / (float)NSAMP;
                const float mean = s * inv;
                const float var  = q * inv - mean * mean;
                const float sc   = gamma[c] * rsqrtf(var + BN_EPS_F);
                g_scale[c] = sc;
                g_shift[c] = beta[c] - mean * sc;
            }
        }
    }
    grid_sync();                               // scale/shift visible everywhere

    // ---- normalize + ReLU: 512 float4 per block ----
    const float4* yv = (const float4*)g_y;
    float4*       ov = (float4*)out;
#pragma unroll
    for (int i = 0; i < 2; ++i) {
        const int idx = blockIdx.x * 512 + i * 256 + threadIdx.x;
        float4 v = yv[idx];
        const int c0 = (idx & 31) * 4;
        v.x = fmaxf(0.f, fmaf(v.x, g_scale[c0 + 0], g_shift[c0 + 0]));
        v.y = fmaxf(0.f, fmaf(v.y, g_scale[c0 + 1], g_shift[c0 + 1]));
        v.z = fmaxf(0.f, fmaf(v.z, g_scale[c0 + 2], g_shift[c0 + 2]));
        v.w = fmaxf(0.f, fmaf(v.w, g_scale[c0 + 3], g_shift[c0 + 3]));
        ov[idx] = v;
    }
}

// ---------------- launch ----------------
extern "C" void kernel_launch(void* const* d_in, const int* in_sizes, int n_in,
                              void* d_out, int out_size) {
    const float* x     = (const float*)d_in[0];
    const float* x0    = (const float*)d_in[1];
    const float* adj   = (const float*)d_in[2];
    const float* W     = (const float*)d_in[3];
    const float* W0    = (const float*)d_in[4];
    const float* gamma = (const float*)d_in[5];
    const float* beta  = (const float*)d_in[6];
    float* out = (float*)d_out;

    pre_kernel<<<GEMM_BLOCKS + N_NODES / 8, 256>>>(x, x0, W, W0, adj);
    post_kernel<<<NBLK, 256>>>(gamma, beta, out);   // 4 iterates + BN + norm
}

// round 12
// speedup vs baseline: 1.0241x; 1.0241x over previous
#include <cuda_runtime.h>
#include <cuda_fp16.h>

#define N_NODES   8192
#define B_BATCH   2
#define D_IN      64
#define D_OUT     32
#define K_ITERS   4
#define C_CH      (K_ITERS * D_OUT)   // 128
#define ALPHA_F   0.1f
#define OMA_F     0.9f
#define BN_EPS_F  1e-5f
#define MAX_NNZ   128
#define NSAMP     (B_BATCH * N_NODES)
#define NBLK      1024                 // 8 rows per block, warp per row

// ---------------- device scratch ----------------
__device__ __half2 g_hkA[N_NODES * D_OUT];               // ping [n][f] -> (b0,b1)
__device__ __half2 g_hkB[N_NODES * D_OUT];               // pong
__device__ float2  g_h0 [N_NODES * D_OUT];               // alpha*(x0@W0)
__device__ int4    g_cv4[(size_t)N_NODES * MAX_NNZ / 2]; // {col*32,val}x2
__device__ int     g_cnt[N_NODES];                       // padded to mult of 8
__device__ float   g_y  [(size_t)B_BATCH * N_NODES * C_CH];
__device__ float   g_psum[K_ITERS * NBLK * D_OUT];
__device__ float   g_psq [K_ITERS * NBLK * D_OUT];
__device__ float   g_scale[C_CH];
__device__ float   g_shift[C_CH];
__device__ int     g_bar = 0;                            // barrier arrivals
__device__ int     g_gen = 0;                            // barrier generation

// device-wide sense barrier (all NBLK blocks resident by construction)
__device__ __forceinline__ void grid_sync() {
    __syncthreads();
    if (threadIdx.x == 0) {
        __threadfence();
        const int my = *(volatile int*)&g_gen;
        if (atomicAdd(&g_bar, 1) == NBLK - 1) {
            atomicExch(&g_bar, 0);
            __threadfence();
            atomicAdd(&g_gen, 1);
        } else {
            while (*(volatile int*)&g_gen == my) { }
        }
        __threadfence();
    }
    __syncthreads();
}

// ---------------- 1) projections: warp per node row, direct x loads ----------
__global__ void gemm_kernel(const float* __restrict__ x,
                            const float* __restrict__ x0,
                            const float* __restrict__ W,
                            const float* __restrict__ W0) {
    __shared__ float Ws [D_IN * D_OUT];    // [d][f]
    __shared__ float W0s[D_IN * D_OUT];

    const int t = threadIdx.x;
    for (int i = t; i < D_IN * D_OUT; i += 256) { Ws[i] = W[i]; W0s[i] = W0[i]; }
    __syncthreads();

    const int warp = t >> 5;
    const int f    = t & 31;
    const int r    = blockIdx.x * 8 + warp;

    const float4* xA = (const float4*)(x  + (size_t)r * D_IN);
    const float4* xB = (const float4*)(x  + (size_t)(N_NODES + r) * D_IN);
    const float4* zA = (const float4*)(x0 + (size_t)r * D_IN);
    const float4* zB = (const float4*)(x0 + (size_t)(N_NODES + r) * D_IN);

    float ha = 0.f, hb = 0.f, za = 0.f, zb = 0.f;
#pragma unroll
    for (int d4 = 0; d4 < D_IN / 4; ++d4) {
        const float4 a = __ldg(&xA[d4]);   // warp-uniform, 1 wavefront
        const float4 b = __ldg(&xB[d4]);
        const float4 c = __ldg(&zA[d4]);
        const float4 e = __ldg(&zB[d4]);
#pragma unroll
        for (int j = 0; j < 4; ++j) {
            const int d = d4 * 4 + j;
            const float w  = Ws [d * D_OUT + f];   // conflict-free LDS
            const float w0 = W0s[d * D_OUT + f];
            const float av = j == 0 ? a.x : j == 1 ? a.y : j == 2 ? a.z : a.w;
            const float bv = j == 0 ? b.x : j == 1 ? b.y : j == 2 ? b.z : b.w;
            const float cv = j == 0 ? c.x : j == 1 ? c.y : j == 2 ? c.z : c.w;
            const float ev = j == 0 ? e.x : j == 1 ? e.y : j == 2 ? e.z : e.w;
            ha = fmaf(av, w,  ha);
            hb = fmaf(bv, w,  hb);
            za = fmaf(cv, w0, za);
            zb = fmaf(ev, w0, zb);
        }
    }
    g_hkA[r * D_OUT + f] = __floats2half2_rn(ha, hb);
    g_h0 [r * D_OUT + f] = make_float2(za * ALPHA_F, zb * ALPHA_F);
}

// ---------------- 2) fused CSR-build + first SpMM iterate --------------------
__global__ void csr_spmm1_kernel(const float* __restrict__ adj) {
    __shared__ int2  meta[8][MAX_NNZ];         // 8 KB: per-warp row metadata
    __shared__ float shs[8][32];
    __shared__ float shq[8][32];

    const int warp = threadIdx.x >> 5;
    const int lane = threadIdx.x & 31;
    const int r    = blockIdx.x * 8 + warp;

    // ---- CSR build (col stored pre-multiplied by D_OUT) ----
    const float4* row = (const float4*)(adj + (size_t)r * N_NODES);
    int2* out = (int2*)&g_cv4[(size_t)r * (MAX_NNZ / 2)];
    int base = 0;

    for (int ch = 0; ch < N_NODES / 128; ch += 2) {
        float4 vA = __ldcs(&row[ch * 32 + lane]);
        float4 vB = __ldcs(&row[(ch + 1) * 32 + lane]);
#pragma unroll
        for (int half = 0; half < 2; ++half) {
            const float4 v = half ? vB : vA;
            const bool any = (v.x != 0.f) | (v.y != 0.f) | (v.z != 0.f) | (v.w != 0.f);
            const unsigned am = __ballot_sync(0xffffffffu, any);
            if (am == 0u) continue;                 // uniform branch
            const float e[4] = {v.x, v.y, v.z, v.w};
#pragma unroll
            for (int k = 0; k < 4; ++k) {
                const bool nz = (e[k] != 0.0f);
                const unsigned m = __ballot_sync(0xffffffffu, nz);
                if (nz) {
                    int pos = base + __popc(m & ((1u << lane) - 1u));
                    if (pos < MAX_NNZ) {
                        const int2 cvp = make_int2(((ch + half) * 128 + lane * 4 + k) << 5,
                                                   __float_as_int(e[k] * OMA_F));
                        meta[warp][pos] = cvp;      // smem copy for iterate 1
                        out[pos] = cvp;             // global copy for iterates 2-4
                    }
                }
                base += __popc(m);
            }
        }
    }
    int cnt  = base < MAX_NNZ ? base : MAX_NNZ;
    int cntp = (cnt + 7) & ~7;
    for (int j = cnt + lane; j < cntp; j += 32) {
        meta[warp][j] = make_int2(0, 0);
        out[j] = make_int2(0, 0);                    // val = 0 padding
    }
    if (lane == 0) g_cnt[r] = cntp;
    __syncwarp();

    // ---- SpMM iterate 1 (meta already in smem) ----
    const int4* mp = (const int4*)meta[warp];
    const int nIt = cntp >> 3;
    const float2 h0 = __ldg(&g_h0[r * D_OUT + lane]);
    float acc0 = h0.x, acc1 = h0.y;
    const __half2* __restrict__ src = g_hkA;

    for (int it = 0; it < nIt; ++it) {
        const int4 a = mp[it * 4 + 0];
        const int4 b = mp[it * 4 + 1];
        const int4 c = mp[it * 4 + 2];
        const int4 d = mp[it * 4 + 3];

        const __half2 g0 = __ldg(&src[a.x + lane]);
        const __half2 g1 = __ldg(&src[a.z + lane]);
        const __half2 g2 = __ldg(&src[b.x + lane]);
        const __half2 g3 = __ldg(&src[b.z + lane]);
        const __half2 g4 = __ldg(&src[c.x + lane]);
        const __half2 g5 = __ldg(&src[c.z + lane]);
        const __half2 g6 = __ldg(&src[d.x + lane]);
        const __half2 g7 = __ldg(&src[d.z + lane]);

        float2 f;
        f = __half22float2(g0); acc0 = fmaf(__int_as_float(a.y), f.x, acc0); acc1 = fmaf(__int_as_float(a.y), f.y, acc1);
        f = __half22float2(g1); acc0 = fmaf(__int_as_float(a.w), f.x, acc0); acc1 = fmaf(__int_as_float(a.w), f.y, acc1);
        f = __half22float2(g2); acc0 = fmaf(__int_as_float(b.y), f.x, acc0); acc1 = fmaf(__int_as_float(b.y), f.y, acc1);
        f = __half22float2(g3); acc0 = fmaf(__int_as_float(b.w), f.x, acc0); acc1 = fmaf(__int_as_float(b.w), f.y, acc1);
        f = __half22float2(g4); acc0 = fmaf(__int_as_float(c.y), f.x, acc0); acc1 = fmaf(__int_as_float(c.y), f.y, acc1);
        f = __half22float2(g5); acc0 = fmaf(__int_as_float(c.w), f.x, acc0); acc1 = fmaf(__int_as_float(c.w), f.y, acc1);
        f = __half22float2(g6); acc0 = fmaf(__int_as_float(d.y), f.x, acc0); acc1 = fmaf(__int_as_float(d.y), f.y, acc1);
        f = __half22float2(g7); acc0 = fmaf(__int_as_float(d.w), f.x, acc0); acc1 = fmaf(__int_as_float(d.w), f.y, acc1);
    }

    g_hkB[r * D_OUT + lane] = __floats2half2_rn(acc0, acc1);
    g_y[(size_t)r * C_CH + lane]             = acc0;
    g_y[(size_t)(N_NODES + r) * C_CH + lane] = acc1;

    shs[warp][lane] = acc0 + acc1;
    shq[warp][lane] = fmaf(acc0, acc0, acc1 * acc1);
    __syncthreads();
    if (warp == 0) {
        float s = 0.f;
#pragma unroll
        for (int w = 0; w < 8; ++w) s += shs[w][lane];
        g_psum[blockIdx.x * D_OUT + lane] = s;
    }
    if (warp == 1) {
        float q = 0.f;
#pragma unroll
        for (int w = 0; w < 8; ++w) q += shq[w][lane];
        g_psq[blockIdx.x * D_OUT + lane] = q;
    }
}

// ---------------- 3) persistent: iterates 2-4 + BN + norm + ReLU -------------
__global__ void __launch_bounds__(256, 8)
post_kernel(const float* __restrict__ gamma,
            const float* __restrict__ beta,
            float* __restrict__ out) {
    __shared__ int4  meta[8][MAX_NNZ / 2];     // 8 KB
    __shared__ float shs[8][32];
    __shared__ float shq[8][32];

    const int warp = threadIdx.x >> 5;
    const int lane = threadIdx.x & 31;
    const int r    = blockIdx.x * 8 + warp;

    // stage metadata ONCE for all 3 iterates
    const int4* __restrict__ cv = g_cv4 + (size_t)r * (MAX_NNZ / 2);
    meta[warp][lane]      = __ldg(&cv[lane]);
    meta[warp][lane + 32] = __ldg(&cv[lane + 32]);
    const int nIt = g_cnt[r] >> 2;             // groups of 4 nnz
    const float2 h0 = __ldg(&g_h0[r * D_OUT + lane]);
    __syncwarp();

    for (int k = 1; k < 4; ++k) {
        const __half2* __restrict__ src = (k & 1) ? g_hkB : g_hkA;
        __half2* __restrict__ dst       = (k & 1) ? g_hkA : g_hkB;

        float acc0 = h0.x, acc1 = h0.y;
#pragma unroll 2
        for (int it = 0; it < nIt; ++it) {
            const int4 a = meta[warp][it * 2 + 0];   // uniform LDS.128
            const int4 b = meta[warp][it * 2 + 1];

            const __half2 g0 = __ldg(&src[a.x + lane]);
            const __half2 g1 = __ldg(&src[a.z + lane]);
            const __half2 g2 = __ldg(&src[b.x + lane]);
            const __half2 g3 = __ldg(&src[b.z + lane]);

            float2 f;
            f = __half22float2(g0); acc0 = fmaf(__int_as_float(a.y), f.x, acc0); acc1 = fmaf(__int_as_float(a.y), f.y, acc1);
            f = __half22float2(g1); acc0 = fmaf(__int_as_float(a.w), f.x, acc0); acc1 = fmaf(__int_as_float(a.w), f.y, acc1);
            f = __half22float2(g2); acc0 = fmaf(__int_as_float(b.y), f.x, acc0); acc1 = fmaf(__int_as_float(b.y), f.y, acc1);
            f = __half22float2(g3); acc0 = fmaf(__int_as_float(b.w), f.x, acc0); acc1 = fmaf(__int_as_float(b.w), f.y, acc1);
        }

        if (k < 3)
            dst[r * D_OUT + lane] = __floats2half2_rn(acc0, acc1);
        g_y[(size_t)r * C_CH + k * D_OUT + lane]             = acc0;
        g_y[(size_t)(N_NODES + r) * C_CH + k * D_OUT + lane] = acc1;

        shs[warp][lane] = acc0 + acc1;
        shq[warp][lane] = fmaf(acc0, acc0, acc1 * acc1);
        __syncthreads();
        if (warp == 0) {
            float s = 0.f;
#pragma unroll
            for (int w = 0; w < 8; ++w) s += shs[w][lane];
            g_psum[(k * NBLK + blockIdx.x) * D_OUT + lane] = s;
        }
        if (warp == 1) {
            float q = 0.f;
#pragma unroll
            for (int w = 0; w < 8; ++w) q += shq[w][lane];
            g_psq[(k * NBLK + blockIdx.x) * D_OUT + lane] = q;
        }
        grid_sync();                           // hk + partials visible everywhere
    }

    // ---- BN finalize: block c (c < 128) owns channel c ----
    if (blockIdx.x < C_CH) {
        const int c     = blockIdx.x;
        const int slice = c >> 5;
        const int ln    = c & 31;
        const int t     = threadIdx.x;
        float s = 0.f, q = 0.f;
        for (int j = t; j < NBLK; j += 256) {
            s += g_psum[(slice * NBLK + j) * D_OUT + ln];
            q += g_psq [(slice * NBLK + j) * D_OUT + ln];
        }
        float* fs = &shs[0][0];
        float* fq = &shq[0][0];
        fs[t] = s; fq[t] = q;
        __syncthreads();
        if (t < 128) { fs[t] += fs[t + 128]; fq[t] += fq[t + 128]; }
        __syncthreads();
        if (t < 64)  { fs[t] += fs[t + 64];  fq[t] += fq[t + 64];  }
        __syncthreads();
        if (t < 32) {
            s = fs[t] + fs[t + 32];
            q = fq[t] + fq[t + 32];
#pragma unroll
            for (int off = 16; off > 0; off >>= 1) {
                s += __shfl_down_sync(0xffffffffu, s, off);
                q += __shfl_down_sync(0xffffffffu, q, off);
            }
            if (t == 0) {
                const float inv  = 1.0f / (float)NSAMP;
                const float mean = s * inv;
                const float var  = q * inv - mean * mean;
                const float sc   = gamma[c] * rsqrtf(var + BN_EPS_F);
                g_scale[c] = sc;
                g_shift[c] = beta[c] - mean * sc;
            }
        }
    }
    grid_sync();                               // scale/shift visible everywhere

    // ---- normalize + ReLU: 512 float4 per block ----
    const float4* yv = (const float4*)g_y;
    float4*       ov = (float4*)out;
#pragma unroll
    for (int i = 0; i < 2; ++i) {
        const int idx = blockIdx.x * 512 + i * 256 + threadIdx.x;
        float4 v = yv[idx];
        const int c0 = (idx & 31) * 4;
        v.x = fmaxf(0.f, fmaf(v.x, g_scale[c0 + 0], g_shift[c0 + 0]));
        v.y = fmaxf(0.f, fmaf(v.y, g_scale[c0 + 1], g_shift[c0 + 1]));
        v.z = fmaxf(0.f, fmaf(v.z, g_scale[c0 + 2], g_shift[c0 + 2]));
        v.w = fmaxf(0.f, fmaf(v.w, g_scale[c0 + 3], g_shift[c0 + 3]));
        ov[idx] = v;
    }
}

// ---------------- launch ----------------
extern "C" void kernel_launch(void* const* d_in, const int* in_sizes, int n_in,
                              void* d_out, int out_size) {
    const float* x     = (const float*)d_in[0];
    const float* x0    = (const float*)d_in[1];
    const float* adj   = (const float*)d_in[2];
    const float* W     = (const float*)d_in[3];
    const float* W0    = (const float*)d_in[4];
    const float* gamma = (const float*)d_in[5];
    const float* beta  = (const float*)d_in[6];
    float* out = (float*)d_out;

    gemm_kernel<<<N_NODES / 8, 256>>>(x, x0, W, W0);
    csr_spmm1_kernel<<<N_NODES / 8, 256>>>(adj);     // scan + iterate 1
    post_kernel<<<NBLK, 256>>>(gamma, beta, out);    // iterates 2-4 + BN + norm
}

// round 13
// speedup vs baseline: 1.1034x; 1.0774x over previous
#include <cuda_runtime.h>
#include <cuda_fp16.h>

#define N_NODES   8192
#define B_BATCH   2
#define D_IN      64
#define D_OUT     32
#define K_ITERS   4
#define C_CH      (K_ITERS * D_OUT)   // 128
#define ALPHA_F   0.1f
#define OMA_F     0.9f
#define BN_EPS_F  1e-5f
#define MAX_NNZ   128
#define NSAMP     (B_BATCH * N_NODES)
#define NBLK      1024                 // 8 rows per block, warp per row

// ---------------- device scratch ----------------
__device__ __half2 g_hkA[N_NODES * D_OUT];               // ping [n][f] -> (b0,b1)
__device__ __half2 g_hkB[N_NODES * D_OUT];               // pong
__device__ float2  g_h0 [N_NODES * D_OUT];               // alpha*(x0@W0)
__device__ int4    g_cv4[(size_t)N_NODES * MAX_NNZ / 2]; // {col*32,val}x2
__device__ int     g_cnt[N_NODES];                       // padded to mult of 8
__device__ float   g_y  [(size_t)B_BATCH * N_NODES * C_CH];
__device__ float   g_psum[K_ITERS * NBLK * D_OUT];
__device__ float   g_psq [K_ITERS * NBLK * D_OUT];
__device__ float   g_scale[C_CH];
__device__ float   g_shift[C_CH];
__device__ int     g_bar = 0;                            // barrier arrivals
__device__ int     g_gen = 0;                            // barrier generation

// device-wide sense barrier (all NBLK blocks resident by construction)
__device__ __forceinline__ void grid_sync() {
    __syncthreads();
    if (threadIdx.x == 0) {
        __threadfence();
        const int my = *(volatile int*)&g_gen;
        if (atomicAdd(&g_bar, 1) == NBLK - 1) {
            atomicExch(&g_bar, 0);
            __threadfence();
            atomicAdd(&g_gen, 1);
        } else {
            while (*(volatile int*)&g_gen == my) { }
        }
        __threadfence();
    }
    __syncthreads();
}

// ---------------- 1) projections: weights in registers, x via uniform LDS ----
// Lane = output feature. Each lane holds its whole weight column (64 regs).
// Blocks [0,128): h = x@W -> g_hkA.   Blocks [128,256): h0 = alpha*(x0@W0).
// Per row-pair: 32 uniform LDS.128 broadcasts + 128 FMA for 64 outputs.
__global__ void gemm_kernel(const float* __restrict__ x,
                            const float* __restrict__ x0,
                            const float* __restrict__ W,
                            const float* __restrict__ W0) {
    __shared__ float4 xs[2][64][D_IN / 4];   // [batch][row][d4]  32 KB

    const int  t     = threadIdx.x;
    const bool isW0  = blockIdx.x >= 128;
    const int  rBase = (blockIdx.x & 127) * 64;

    const float* __restrict__ xg = isW0 ? x0 : x;
    const float* __restrict__ Wg = isW0 ? W0 : W;

    // stage 64 node-rows x 2 batches (coalesced float4)
    const float4* xg0 = (const float4*)(xg + (size_t)rBase * D_IN);
    const float4* xg1 = (const float4*)(xg + (size_t)(N_NODES + rBase) * D_IN);
    for (int i = t; i < 64 * (D_IN / 4); i += 256) {
        const int row = i >> 4, d4 = i & 15;
        xs[0][row][d4] = __ldg(&xg0[i]);
        xs[1][row][d4] = __ldg(&xg1[i]);
    }

    // weight column into registers (coalesced scalar loads across lanes)
    const int lane = t & 31;
    const int warp = t >> 5;
    float w[D_IN];
#pragma unroll
    for (int d = 0; d < D_IN; ++d)
        w[d] = __ldg(&Wg[d * D_OUT + lane]);
    __syncthreads();

    // each warp computes 8 node-rows (both batches)
#pragma unroll
    for (int j = 0; j < 8; ++j) {
        const int row = warp * 8 + j;
        float acc0 = 0.f, acc1 = 0.f;
#pragma unroll
        for (int d4 = 0; d4 < D_IN / 4; ++d4) {
            const float4 a = xs[0][row][d4];   // uniform LDS.128 broadcast
            const float4 b = xs[1][row][d4];
            acc0 = fmaf(a.x, w[d4 * 4 + 0], acc0);
            acc1 = fmaf(b.x, w[d4 * 4 + 0], acc1);
            acc0 = fmaf(a.y, w[d4 * 4 + 1], acc0);
            acc1 = fmaf(b.y, w[d4 * 4 + 1], acc1);
            acc0 = fmaf(a.z, w[d4 * 4 + 2], acc0);
            acc1 = fmaf(b.z, w[d4 * 4 + 2], acc1);
            acc0 = fmaf(a.w, w[d4 * 4 + 3], acc0);
            acc1 = fmaf(b.w, w[d4 * 4 + 3], acc1);
        }
        const int r = rBase + row;
        if (!isW0)
            g_hkA[r * D_OUT + lane] = __floats2half2_rn(acc0, acc1);
        else
            g_h0 [r * D_OUT + lane] = make_float2(acc0 * ALPHA_F, acc1 * ALPHA_F);
    }
}

// ---------------- 2) fused CSR-build + first SpMM iterate --------------------
__global__ void csr_spmm1_kernel(const float* __restrict__ adj) {
    __shared__ int2  meta[8][MAX_NNZ];         // 8 KB: per-warp row metadata
    __shared__ float shs[8][32];
    __shared__ float shq[8][32];

    const int warp = threadIdx.x >> 5;
    const int lane = threadIdx.x & 31;
    const int r    = blockIdx.x * 8 + warp;

    // ---- CSR build (col stored pre-multiplied by D_OUT) ----
    const float4* row = (const float4*)(adj + (size_t)r * N_NODES);
    int2* out = (int2*)&g_cv4[(size_t)r * (MAX_NNZ / 2)];
    int base = 0;

    for (int ch = 0; ch < N_NODES / 128; ch += 2) {
        float4 vA = __ldcs(&row[ch * 32 + lane]);
        float4 vB = __ldcs(&row[(ch + 1) * 32 + lane]);
#pragma unroll
        for (int half = 0; half < 2; ++half) {
            const float4 v = half ? vB : vA;
            const bool any = (v.x != 0.f) | (v.y != 0.f) | (v.z != 0.f) | (v.w != 0.f);
            const unsigned am = __ballot_sync(0xffffffffu, any);
            if (am == 0u) continue;                 // uniform branch
            const float e[4] = {v.x, v.y, v.z, v.w};
#pragma unroll
            for (int k = 0; k < 4; ++k) {
                const bool nz = (e[k] != 0.0f);
                const unsigned m = __ballot_sync(0xffffffffu, nz);
                if (nz) {
                    int pos = base + __popc(m & ((1u << lane) - 1u));
                    if (pos < MAX_NNZ) {
                        const int2 cvp = make_int2(((ch + half) * 128 + lane * 4 + k) << 5,
                                                   __float_as_int(e[k] * OMA_F));
                        meta[warp][pos] = cvp;      // smem copy for iterate 1
                        out[pos] = cvp;             // global copy for iterates 2-4
                    }
                }
                base += __popc(m);
            }
        }
    }
    int cnt  = base < MAX_NNZ ? base : MAX_NNZ;
    int cntp = (cnt + 7) & ~7;
    for (int j = cnt + lane; j < cntp; j += 32) {
        meta[warp][j] = make_int2(0, 0);
        out[j] = make_int2(0, 0);                    // val = 0 padding
    }
    if (lane == 0) g_cnt[r] = cntp;
    __syncwarp();

    // ---- SpMM iterate 1 (meta already in smem) ----
    const int4* mp = (const int4*)meta[warp];
    const int nIt = cntp >> 3;
    const float2 h0 = __ldg(&g_h0[r * D_OUT + lane]);
    float acc0 = h0.x, acc1 = h0.y;
    const __half2* __restrict__ src = g_hkA;

    for (int it = 0; it < nIt; ++it) {
        const int4 a = mp[it * 4 + 0];
        const int4 b = mp[it * 4 + 1];
        const int4 c = mp[it * 4 + 2];
        const int4 d = mp[it * 4 + 3];

        const __half2 g0 = __ldg(&src[a.x + lane]);
        const __half2 g1 = __ldg(&src[a.z + lane]);
        const __half2 g2 = __ldg(&src[b.x + lane]);
        const __half2 g3 = __ldg(&src[b.z + lane]);
        const __half2 g4 = __ldg(&src[c.x + lane]);
        const __half2 g5 = __ldg(&src[c.z + lane]);
        const __half2 g6 = __ldg(&src[d.x + lane]);
        const __half2 g7 = __ldg(&src[d.z + lane]);

        float2 f;
        f = __half22float2(g0); acc0 = fmaf(__int_as_float(a.y), f.x, acc0); acc1 = fmaf(__int_as_float(a.y), f.y, acc1);
        f = __half22float2(g1); acc0 = fmaf(__int_as_float(a.w), f.x, acc0); acc1 = fmaf(__int_as_float(a.w), f.y, acc1);
        f = __half22float2(g2); acc0 = fmaf(__int_as_float(b.y), f.x, acc0); acc1 = fmaf(__int_as_float(b.y), f.y, acc1);
        f = __half22float2(g3); acc0 = fmaf(__int_as_float(b.w), f.x, acc0); acc1 = fmaf(__int_as_float(b.w), f.y, acc1);
        f = __half22float2(g4); acc0 = fmaf(__int_as_float(c.y), f.x, acc0); acc1 = fmaf(__int_as_float(c.y), f.y, acc1);
        f = __half22float2(g5); acc0 = fmaf(__int_as_float(c.w), f.x, acc0); acc1 = fmaf(__int_as_float(c.w), f.y, acc1);
        f = __half22float2(g6); acc0 = fmaf(__int_as_float(d.y), f.x, acc0); acc1 = fmaf(__int_as_float(d.y), f.y, acc1);
        f = __half22float2(g7); acc0 = fmaf(__int_as_float(d.w), f.x, acc0); acc1 = fmaf(__int_as_float(d.w), f.y, acc1);
    }

    g_hkB[r * D_OUT + lane] = __floats2half2_rn(acc0, acc1);
    g_y[(size_t)r * C_CH + lane]             = acc0;
    g_y[(size_t)(N_NODES + r) * C_CH + lane] = acc1;

    shs[warp][lane] = acc0 + acc1;
    shq[warp][lane] = fmaf(acc0, acc0, acc1 * acc1);
    __syncthreads();
    if (warp == 0) {
        float s = 0.f;
#pragma unroll
        for (int w = 0; w < 8; ++w) s += shs[w][lane];
        g_psum[blockIdx.x * D_OUT + lane] = s;
    }
    if (warp == 1) {
        float q = 0.f;
#pragma unroll
        for (int w = 0; w < 8; ++w) q += shq[w][lane];
        g_psq[blockIdx.x * D_OUT + lane] = q;
    }
}

// ---------------- 3) persistent: iterates 2-4 + BN + norm + ReLU -------------
__global__ void __launch_bounds__(256, 8)
post_kernel(const float* __restrict__ gamma,
            const float* __restrict__ beta,
            float* __restrict__ out) {
    __shared__ int4  meta[8][MAX_NNZ / 2];     // 8 KB
    __shared__ float shs[8][32];
    __shared__ float shq[8][32];

    const int warp = threadIdx.x >> 5;
    const int lane = threadIdx.x & 31;
    const int r    = blockIdx.x * 8 + warp;

    // stage metadata ONCE for all 3 iterates
    const int4* __restrict__ cv = g_cv4 + (size_t)r * (MAX_NNZ / 2);
    meta[warp][lane]      = __ldg(&cv[lane]);
    meta[warp][lane + 32] = __ldg(&cv[lane + 32]);
    const int nIt = g_cnt[r] >> 2;             // groups of 4 nnz
    const float2 h0 = __ldg(&g_h0[r * D_OUT + lane]);
    __syncwarp();

    for (int k = 1; k < 4; ++k) {
        const __half2* __restrict__ src = (k & 1) ? g_hkB : g_hkA;
        __half2* __restrict__ dst       = (k & 1) ? g_hkA : g_hkB;

        float acc0 = h0.x, acc1 = h0.y;
#pragma unroll 2
        for (int it = 0; it < nIt; ++it) {
            const int4 a = meta[warp][it * 2 + 0];   // uniform LDS.128
            const int4 b = meta[warp][it * 2 + 1];

            const __half2 g0 = __ldg(&src[a.x + lane]);
            const __half2 g1 = __ldg(&src[a.z + lane]);
            const __half2 g2 = __ldg(&src[b.x + lane]);
            const __half2 g3 = __ldg(&src[b.z + lane]);

            float2 f;
            f = __half22float2(g0); acc0 = fmaf(__int_as_float(a.y), f.x, acc0); acc1 = fmaf(__int_as_float(a.y), f.y, acc1);
            f = __half22float2(g1); acc0 = fmaf(__int_as_float(a.w), f.x, acc0); acc1 = fmaf(__int_as_float(a.w), f.y, acc1);
            f = __half22float2(g2); acc0 = fmaf(__int_as_float(b.y), f.x, acc0); acc1 = fmaf(__int_as_float(b.y), f.y, acc1);
            f = __half22float2(g3); acc0 = fmaf(__int_as_float(b.w), f.x, acc0); acc1 = fmaf(__int_as_float(b.w), f.y, acc1);
        }

        if (k < 3)
            dst[r * D_OUT + lane] = __floats2half2_rn(acc0, acc1);
        g_y[(size_t)r * C_CH + k * D_OUT + lane]             = acc0;
        g_y[(size_t)(N_NODES + r) * C_CH + k * D_OUT + lane] = acc1;

        shs[warp][lane] = acc0 + acc1;
        shq[warp][lane] = fmaf(acc0, acc0, acc1 * acc1);
        __syncthreads();
        if (warp == 0) {
            float s = 0.f;
#pragma unroll
            for (int w = 0; w < 8; ++w) s += shs[w][lane];
            g_psum[(k * NBLK + blockIdx.x) * D_OUT + lane] = s;
        }
        if (warp == 1) {
            float q = 0.f;
#pragma unroll
            for (int w = 0; w < 8; ++w) q += shq[w][lane];
            g_psq[(k * NBLK + blockIdx.x) * D_OUT + lane] = q;
        }
        grid_sync();                           // hk + partials visible everywhere
    }

    // ---- BN finalize: block c (c < 128) owns channel c ----
    if (blockIdx.x < C_CH) {
        const int c     = blockIdx.x;
        const int slice = c >> 5;
        const int ln    = c & 31;
        const int t     = threadIdx.x;
        float s = 0.f, q = 0.f;
        for (int j = t; j < NBLK; j += 256) {
            s += g_psum[(slice * NBLK + j) * D_OUT + ln];
            q += g_psq [(slice * NBLK + j) * D_OUT + ln];
        }
        float* fs = &shs[0][0];
        float* fq = &shq[0][0];
        fs[t] = s; fq[t] = q;
        __syncthreads();
        if (t < 128) { fs[t] += fs[t + 128]; fq[t] += fq[t + 128]; }
        __syncthreads();
        if (t < 64)  { fs[t] += fs[t + 64];  fq[t] += fq[t + 64];  }
        __syncthreads();
        if (t < 32) {
            s = fs[t] + fs[t + 32];
            q = fq[t] + fq[t + 32];
#pragma unroll
            for (int off = 16; off > 0; off >>= 1) {
                s += __shfl_down_sync(0xffffffffu, s, off);
                q += __shfl_down_sync(0xffffffffu, q, off);
            }
            if (t == 0) {
                const float inv  = 1.0f / (float)NSAMP;
                const float mean = s * inv;
                const float var  = q * inv - mean * mean;
                const float sc   = gamma[c] * rsqrtf(var + BN_EPS_F);
                g_scale[c] = sc;
                g_shift[c] = beta[c] - mean * sc;
            }
        }
    }
    grid_sync();                               // scale/shift visible everywhere

    // ---- normalize + ReLU: 512 float4 per block ----
    const float4* yv = (const float4*)g_y;
    float4*       ov = (float4*)out;
#pragma unroll
    for (int i = 0; i < 2; ++i) {
        const int idx = blockIdx.x * 512 + i * 256 + threadIdx.x;
        float4 v = yv[idx];
        const int c0 = (idx & 31) * 4;
        v.x = fmaxf(0.f, fmaf(v.x, g_scale[c0 + 0], g_shift[c0 + 0]));
        v.y = fmaxf(0.f, fmaf(v.y, g_scale[c0 + 1], g_shift[c0 + 1]));
        v.z = fmaxf(0.f, fmaf(v.z, g_scale[c0 + 2], g_shift[c0 + 2]));
        v.w = fmaxf(0.f, fmaf(v.w, g_scale[c0 + 3], g_shift[c0 + 3]));
        ov[idx] = v;
    }
}

// ---------------- launch ----------------
extern "C" void kernel_launch(void* const* d_in, const int* in_sizes, int n_in,
                              void* d_out, int out_size) {
    const float* x     = (const float*)d_in[0];
    const float* x0    = (const float*)d_in[1];
    const float* adj   = (const float*)d_in[2];
    const float* W     = (const float*)d_in[3];
    const float* W0    = (const float*)d_in[4];
    const float* gamma = (const float*)d_in[5];
    const float* beta  = (const float*)d_in[6];
    float* out = (float*)d_out;

    gemm_kernel<<<256, 256>>>(x, x0, W, W0);
    csr_spmm1_kernel<<<N_NODES / 8, 256>>>(adj);     // scan + iterate 1
    post_kernel<<<NBLK, 256>>>(gamma, beta, out);    // iterates 2-4 + BN + norm
}

// round 14
// speedup vs baseline: 1.1146x; 1.0101x over previous
#include <cuda_runtime.h>
#include <cuda_fp16.h>

#define N_NODES   8192
#define B_BATCH   2
#define D_IN      64
#define D_OUT     32
#define K_ITERS   4
#define C_CH      (K_ITERS * D_OUT)   // 128
#define ALPHA_F   0.1f
#define OMA_F     0.9f
#define BN_EPS_F  1e-5f
#define MAX_NNZ   128
#define NSAMP     (B_BATCH * N_NODES)
#define NBLK      1024                 // 8 rows per block, warp per row

// ---------------- device scratch ----------------
__device__ __half2 g_hkA[N_NODES * D_OUT];               // ping [n][f] -> (b0,b1)
__device__ __half2 g_hkB[N_NODES * D_OUT];               // pong
__device__ float2  g_h0 [N_NODES * D_OUT];               // alpha*(x0@W0)
__device__ int4    g_cv4[(size_t)N_NODES * MAX_NNZ / 2]; // {col*32,val}x2
__device__ int     g_cnt[N_NODES];                       // padded to mult of 8
__device__ float   g_y  [(size_t)B_BATCH * N_NODES * C_CH];
__device__ float   g_psum[K_ITERS * NBLK * D_OUT];
__device__ float   g_psq [K_ITERS * NBLK * D_OUT];
__device__ float   g_scale[C_CH];
__device__ float   g_shift[C_CH];
__device__ int     g_bar = 0;                            // barrier arrivals
__device__ int     g_gen = 0;                            // barrier generation

// device-wide sense barrier (all NBLK blocks resident by construction)
__device__ __forceinline__ void grid_sync() {
    __syncthreads();
    if (threadIdx.x == 0) {
        __threadfence();
        const int my = *(volatile int*)&g_gen;
        if (atomicAdd(&g_bar, 1) == NBLK - 1) {
            atomicExch(&g_bar, 0);
            __threadfence();
            atomicAdd(&g_gen, 1);
        } else {
            while (*(volatile int*)&g_gen == my) { }
        }
        __threadfence();
    }
    __syncthreads();
}

// ---------------- 1) projections: weights in registers, x via uniform LDS ----
// 64-thread blocks, 16 node-rows each -> grid 1024, ~10 blocks/SM fit the RF.
// Lane = output feature; lane holds its whole weight column in 64 registers.
// Blocks [0,512): h = x@W -> g_hkA.  Blocks [512,1024): h0 = alpha*(x0@W0).
__global__ void gemm_kernel(const float* __restrict__ x,
                            const float* __restrict__ x0,
                            const float* __restrict__ W,
                            const float* __restrict__ W0) {
    __shared__ float4 xs[2][16][D_IN / 4];   // [batch][row][d4]  8 KB

    const int  t     = threadIdx.x;          // 0..63
    const bool isW0  = blockIdx.x >= 512;
    const int  rBase = (blockIdx.x & 511) * 16;

    const float* __restrict__ xg = isW0 ? x0 : x;
    const float* __restrict__ Wg = isW0 ? W0 : W;

    // stage 16 node-rows x 2 batches (coalesced float4)
    const float4* xg0 = (const float4*)(xg + (size_t)rBase * D_IN);
    const float4* xg1 = (const float4*)(xg + (size_t)(N_NODES + rBase) * D_IN);
    for (int i = t; i < 16 * (D_IN / 4); i += 64) {
        const int row = i >> 4, d4 = i & 15;
        xs[0][row][d4] = __ldg(&xg0[i]);
        xs[1][row][d4] = __ldg(&xg1[i]);
    }

    // weight column into registers (coalesced scalar loads across lanes)
    const int lane = t & 31;
    const int warp = t >> 5;
    float w[D_IN];
#pragma unroll
    for (int d = 0; d < D_IN; ++d)
        w[d] = __ldg(&Wg[d * D_OUT + lane]);
    __syncthreads();

    // each warp computes 8 node-rows (both batches)
#pragma unroll
    for (int j = 0; j < 8; ++j) {
        const int row = warp * 8 + j;
        float acc0 = 0.f, acc1 = 0.f;
#pragma unroll
        for (int d4 = 0; d4 < D_IN / 4; ++d4) {
            const float4 a = xs[0][row][d4];   // uniform LDS.128 broadcast
            const float4 b = xs[1][row][d4];
            acc0 = fmaf(a.x, w[d4 * 4 + 0], acc0);
            acc1 = fmaf(b.x, w[d4 * 4 + 0], acc1);
            acc0 = fmaf(a.y, w[d4 * 4 + 1], acc0);
            acc1 = fmaf(b.y, w[d4 * 4 + 1], acc1);
            acc0 = fmaf(a.z, w[d4 * 4 + 2], acc0);
            acc1 = fmaf(b.z, w[d4 * 4 + 2], acc1);
            acc0 = fmaf(a.w, w[d4 * 4 + 3], acc0);
            acc1 = fmaf(b.w, w[d4 * 4 + 3], acc1);
        }
        const int r = rBase + row;
        if (!isW0)
            g_hkA[r * D_OUT + lane] = __floats2half2_rn(acc0, acc1);
        else
            g_h0 [r * D_OUT + lane] = make_float2(acc0 * ALPHA_F, acc1 * ALPHA_F);
    }
}

// ---------------- 2) fused CSR-build + first SpMM iterate --------------------
__global__ void csr_spmm1_kernel(const float* __restrict__ adj) {
    __shared__ int2  meta[8][MAX_NNZ];         // 8 KB: per-warp row metadata
    __shared__ float shs[8][32];
    __shared__ float shq[8][32];

    const int warp = threadIdx.x >> 5;
    const int lane = threadIdx.x & 31;
    const int r    = blockIdx.x * 8 + warp;

    // ---- CSR build (col stored pre-multiplied by D_OUT) ----
    const float4* row = (const float4*)(adj + (size_t)r * N_NODES);
    int2* out = (int2*)&g_cv4[(size_t)r * (MAX_NNZ / 2)];
    int base = 0;

    for (int ch = 0; ch < N_NODES / 128; ch += 2) {
        float4 vA = __ldcs(&row[ch * 32 + lane]);
        float4 vB = __ldcs(&row[(ch + 1) * 32 + lane]);
#pragma unroll
        for (int half = 0; half < 2; ++half) {
            const float4 v = half ? vB : vA;
            const bool any = (v.x != 0.f) | (v.y != 0.f) | (v.z != 0.f) | (v.w != 0.f);
            const unsigned am = __ballot_sync(0xffffffffu, any);
            if (am == 0u) continue;                 // uniform branch
            const float e[4] = {v.x, v.y, v.z, v.w};
#pragma unroll
            for (int k = 0; k < 4; ++k) {
                const bool nz = (e[k] != 0.0f);
                const unsigned m = __ballot_sync(0xffffffffu, nz);
                if (nz) {
                    int pos = base + __popc(m & ((1u << lane) - 1u));
                    if (pos < MAX_NNZ) {
                        const int2 cvp = make_int2(((ch + half) * 128 + lane * 4 + k) << 5,
                                                   __float_as_int(e[k] * OMA_F));
                        meta[warp][pos] = cvp;      // smem copy for iterate 1
                        out[pos] = cvp;             // global copy for iterates 2-4
                    }
                }
                base += __popc(m);
            }
        }
    }
    int cnt  = base < MAX_NNZ ? base : MAX_NNZ;
    int cntp = (cnt + 7) & ~7;
    for (int j = cnt + lane; j < cntp; j += 32) {
        meta[warp][j] = make_int2(0, 0);
        out[j] = make_int2(0, 0);                    // val = 0 padding
    }
    if (lane == 0) g_cnt[r] = cntp;
    __syncwarp();

    // ---- SpMM iterate 1 (meta already in smem) ----
    const int4* mp = (const int4*)meta[warp];
    const int nIt = cntp >> 3;
    const float2 h0 = __ldg(&g_h0[r * D_OUT + lane]);
    float acc0 = h0.x, acc1 = h0.y;
    const __half2* __restrict__ src = g_hkA;

    for (int it = 0; it < nIt; ++it) {
        const int4 a = mp[it * 4 + 0];
        const int4 b = mp[it * 4 + 1];
        const int4 c = mp[it * 4 + 2];
        const int4 d = mp[it * 4 + 3];

        const __half2 g0 = __ldg(&src[a.x + lane]);
        const __half2 g1 = __ldg(&src[a.z + lane]);
        const __half2 g2 = __ldg(&src[b.x + lane]);
        const __half2 g3 = __ldg(&src[b.z + lane]);
        const __half2 g4 = __ldg(&src[c.x + lane]);
        const __half2 g5 = __ldg(&src[c.z + lane]);
        const __half2 g6 = __ldg(&src[d.x + lane]);
        const __half2 g7 = __ldg(&src[d.z + lane]);

        float2 f;
        f = __half22float2(g0); acc0 = fmaf(__int_as_float(a.y), f.x, acc0); acc1 = fmaf(__int_as_float(a.y), f.y, acc1);
        f = __half22float2(g1); acc0 = fmaf(__int_as_float(a.w), f.x, acc0); acc1 = fmaf(__int_as_float(a.w), f.y, acc1);
        f = __half22float2(g2); acc0 = fmaf(__int_as_float(b.y), f.x, acc0); acc1 = fmaf(__int_as_float(b.y), f.y, acc1);
        f = __half22float2(g3); acc0 = fmaf(__int_as_float(b.w), f.x, acc0); acc1 = fmaf(__int_as_float(b.w), f.y, acc1);
        f = __half22float2(g4); acc0 = fmaf(__int_as_float(c.y), f.x, acc0); acc1 = fmaf(__int_as_float(c.y), f.y, acc1);
        f = __half22float2(g5); acc0 = fmaf(__int_as_float(c.w), f.x, acc0); acc1 = fmaf(__int_as_float(c.w), f.y, acc1);
        f = __half22float2(g6); acc0 = fmaf(__int_as_float(d.y), f.x, acc0); acc1 = fmaf(__int_as_float(d.y), f.y, acc1);
        f = __half22float2(g7); acc0 = fmaf(__int_as_float(d.w), f.x, acc0); acc1 = fmaf(__int_as_float(d.w), f.y, acc1);
    }

    g_hkB[r * D_OUT + lane] = __floats2half2_rn(acc0, acc1);
    g_y[(size_t)r * C_CH + lane]             = acc0;
    g_y[(size_t)(N_NODES + r) * C_CH + lane] = acc1;

    shs[warp][lane] = acc0 + acc1;
    shq[warp][lane] = fmaf(acc0, acc0, acc1 * acc1);
    __syncthreads();
    if (warp == 0) {
        float s = 0.f;
#pragma unroll
        for (int w = 0; w < 8; ++w) s += shs[w][lane];
        g_psum[blockIdx.x * D_OUT + lane] = s;
    }
    if (warp == 1) {
        float q = 0.f;
#pragma unroll
        for (int w = 0; w < 8; ++w) q += shq[w][lane];
        g_psq[blockIdx.x * D_OUT + lane] = q;
    }
}

// ---------------- 3) persistent: iterates 2-4 + BN + norm + ReLU -------------
__global__ void __launch_bounds__(256, 8)
post_kernel(const float* __restrict__ gamma,
            const float* __restrict__ beta,
            float* __restrict__ out) {
    __shared__ int4  meta[8][MAX_NNZ / 2];     // 8 KB
    __shared__ float shs[8][32];
    __shared__ float shq[8][32];

    const int warp = threadIdx.x >> 5;
    const int lane = threadIdx.x & 31;
    const int r    = blockIdx.x * 8 + warp;

    // stage metadata ONCE for all 3 iterates
    const int4* __restrict__ cv = g_cv4 + (size_t)r * (MAX_NNZ / 2);
    meta[warp][lane]      = __ldg(&cv[lane]);
    meta[warp][lane + 32] = __ldg(&cv[lane + 32]);
    const int nIt = g_cnt[r] >> 2;             // groups of 4 nnz
    const float2 h0 = __ldg(&g_h0[r * D_OUT + lane]);
    __syncwarp();

    for (int k = 1; k < 4; ++k) {
        const __half2* __restrict__ src = (k & 1) ? g_hkB : g_hkA;
        __half2* __restrict__ dst       = (k & 1) ? g_hkA : g_hkB;

        float acc0 = h0.x, acc1 = h0.y;
#pragma unroll 2
        for (int it = 0; it < nIt; ++it) {
            const int4 a = meta[warp][it * 2 + 0];   // uniform LDS.128
            const int4 b = meta[warp][it * 2 + 1];

            const __half2 g0 = __ldg(&src[a.x + lane]);
            const __half2 g1 = __ldg(&src[a.z + lane]);
            const __half2 g2 = __ldg(&src[b.x + lane]);
            const __half2 g3 = __ldg(&src[b.z + lane]);

            float2 f;
            f = __half22float2(g0); acc0 = fmaf(__int_as_float(a.y), f.x, acc0); acc1 = fmaf(__int_as_float(a.y), f.y, acc1);
            f = __half22float2(g1); acc0 = fmaf(__int_as_float(a.w), f.x, acc0); acc1 = fmaf(__int_as_float(a.w), f.y, acc1);
            f = __half22float2(g2); acc0 = fmaf(__int_as_float(b.y), f.x, acc0); acc1 = fmaf(__int_as_float(b.y), f.y, acc1);
            f = __half22float2(g3); acc0 = fmaf(__int_as_float(b.w), f.x, acc0); acc1 = fmaf(__int_as_float(b.w), f.y, acc1);
        }

        if (k < 3)
            dst[r * D_OUT + lane] = __floats2half2_rn(acc0, acc1);
        g_y[(size_t)r * C_CH + k * D_OUT + lane]             = acc0;
        g_y[(size_t)(N_NODES + r) * C_CH + k * D_OUT + lane] = acc1;

        shs[warp][lane] = acc0 + acc1;
        shq[warp][lane] = fmaf(acc0, acc0, acc1 * acc1);
        __syncthreads();
        if (warp == 0) {
            float s = 0.f;
#pragma unroll
            for (int w = 0; w < 8; ++w) s += shs[w][lane];
            g_psum[(k * NBLK + blockIdx.x) * D_OUT + lane] = s;
        }
        if (warp == 1) {
            float q = 0.f;
#pragma unroll
            for (int w = 0; w < 8; ++w) q += shq[w][lane];
            g_psq[(k * NBLK + blockIdx.x) * D_OUT + lane] = q;
        }
        grid_sync();                           // hk + partials visible everywhere
    }

    // ---- BN finalize: block c (c < 128) owns channel c ----
    if (blockIdx.x < C_CH) {
        const int c     = blockIdx.x;
        const int slice = c >> 5;
        const int ln    = c & 31;
        const int t     = threadIdx.x;
        float s = 0.f, q = 0.f;
        for (int j = t; j < NBLK; j += 256) {
            s += g_psum[(slice * NBLK + j) * D_OUT + ln];
            q += g_psq [(slice * NBLK + j) * D_OUT + ln];
        }
        float* fs = &shs[0][0];
        float* fq = &shq[0][0];
        fs[t] = s; fq[t] = q;
        __syncthreads();
        if (t < 128) { fs[t] += fs[t + 128]; fq[t] += fq[t + 128]; }
        __syncthreads();
        if (t < 64)  { fs[t] += fs[t + 64];  fq[t] += fq[t + 64];  }
        __syncthreads();
        if (t < 32) {
            s = fs[t] + fs[t + 32];
            q = fq[t] + fq[t + 32];
#pragma unroll
            for (int off = 16; off > 0; off >>= 1) {
                s += __shfl_down_sync(0xffffffffu, s, off);
                q += __shfl_down_sync(0xffffffffu, q, off);
            }
            if (t == 0) {
                const float inv  = 1.0f / (float)NSAMP;
                const float mean = s * inv;
                const float var  = q * inv - mean * mean;
                const float sc   = gamma[c] * rsqrtf(var + BN_EPS_F);
                g_scale[c] = sc;
                g_shift[c] = beta[c] - mean * sc;
            }
        }
    }
    grid_sync();                               // scale/shift visible everywhere

    // ---- normalize + ReLU: 512 float4 per block ----
    const float4* yv = (const float4*)g_y;
    float4*       ov = (float4*)out;
#pragma unroll
    for (int i = 0; i < 2; ++i) {
        const int idx = blockIdx.x * 512 + i * 256 + threadIdx.x;
        float4 v = yv[idx];
        const int c0 = (idx & 31) * 4;
        v.x = fmaxf(0.f, fmaf(v.x, g_scale[c0 + 0], g_shift[c0 + 0]));
        v.y = fmaxf(0.f, fmaf(v.y, g_scale[c0 + 1], g_shift[c0 + 1]));
        v.z = fmaxf(0.f, fmaf(v.z, g_scale[c0 + 2], g_shift[c0 + 2]));
        v.w = fmaxf(0.f, fmaf(v.w, g_scale[c0 + 3], g_shift[c0 + 3]));
        ov[idx] = v;
    }
}

// ---------------- launch ----------------
extern "C" void kernel_launch(void* const* d_in, const int* in_sizes, int n_in,
                              void* d_out, int out_size) {
    const float* x     = (const float*)d_in[0];
    const float* x0    = (const float*)d_in[1];
    const float* adj   = (const float*)d_in[2];
    const float* W     = (const float*)d_in[3];
    const float* W0    = (const float*)d_in[4];
    const float* gamma = (const float*)d_in[5];
    const float* beta  = (const float*)d_in[6];
    float* out = (float*)d_out;

    gemm_kernel<<<1024, 64>>>(x, x0, W, W0);
    csr_spmm1_kernel<<<N_NODES / 8, 256>>>(adj);     // scan + iterate 1
    post_kernel<<<NBLK, 256>>>(gamma, beta, out);    // iterates 2-4 + BN + norm
}

// round 15
// speedup vs baseline: 1.1235x; 1.0080x over previous
#include <cuda_runtime.h>
#include <cuda_fp16.h>

#define N_NODES   8192
#define B_BATCH   2
#define D_IN      64
#define D_OUT     32
#define K_ITERS   4
#define C_CH      (K_ITERS * D_OUT)   // 128
#define ALPHA_F   0.1f
#define OMA_F     0.9f
#define BN_EPS_F  1e-5f
#define MAX_NNZ   128
#define NSAMP     (B_BATCH * N_NODES)
#define NBLK      1024                 // 8 rows per block, warp per row

// ---------------- device scratch ----------------
__device__ __half2 g_hkA[N_NODES * D_OUT];               // ping [n][f] -> (b0,b1)
__device__ __half2 g_hkB[N_NODES * D_OUT];               // pong
__device__ float2  g_h0 [N_NODES * D_OUT];               // alpha*(x0@W0)
__device__ int4    g_cv4[(size_t)N_NODES * MAX_NNZ / 2]; // {col*32,val}x2
__device__ int     g_cnt[N_NODES];                       // padded to mult of 8
__device__ float   g_y  [(size_t)B_BATCH * N_NODES * C_CH];
__device__ float   g_psum[K_ITERS * NBLK * D_OUT];
__device__ float   g_psq [K_ITERS * NBLK * D_OUT];
__device__ float   g_scale[C_CH];
__device__ float   g_shift[C_CH];
__device__ int     g_bar = 0;                            // barrier arrivals
__device__ int     g_gen = 0;                            // barrier generation

// device-wide sense barrier (all NBLK blocks resident by construction)
__device__ __forceinline__ void grid_sync() {
    __syncthreads();
    if (threadIdx.x == 0) {
        __threadfence();
        const int my = *(volatile int*)&g_gen;
        if (atomicAdd(&g_bar, 1) == NBLK - 1) {
            atomicExch(&g_bar, 0);
            __threadfence();
            atomicAdd(&g_gen, 1);
        } else {
            while (*(volatile int*)&g_gen == my) { }
        }
        __threadfence();
    }
    __syncthreads();
}

// ---------------- 1) projections: weights in registers, 4 rows per warp ------
// Blocks [0,1024): h = x@W -> g_hkA.  Blocks [1024,2048): h0 = alpha*(x0@W0).
__global__ void gemm_kernel(const float* __restrict__ x,
                            const float* __restrict__ x0,
                            const float* __restrict__ W,
                            const float* __restrict__ W0) {
    __shared__ float4 xs[2][8][D_IN / 4];   // [batch][row][d4]  4 KB

    const int  t     = threadIdx.x;          // 0..63
    const bool isW0  = blockIdx.x >= 1024;
    const int  rBase = (blockIdx.x & 1023) * 8;

    const float* __restrict__ xg = isW0 ? x0 : x;
    const float* __restrict__ Wg = isW0 ? W0 : W;

    // stage 8 node-rows x 2 batches (coalesced float4)
    const float4* xg0 = (const float4*)(xg + (size_t)rBase * D_IN);
    const float4* xg1 = (const float4*)(xg + (size_t)(N_NODES + rBase) * D_IN);
    for (int i = t; i < 8 * (D_IN / 4); i += 64) {
        const int row = i >> 4, d4 = i & 15;
        xs[0][row][d4] = __ldg(&xg0[i]);
        xs[1][row][d4] = __ldg(&xg1[i]);
    }

    // weight column into registers (coalesced scalar loads across lanes)
    const int lane = t & 31;
    const int warp = t >> 5;
    float w[D_IN];
#pragma unroll
    for (int d = 0; d < D_IN; ++d)
        w[d] = __ldg(&Wg[d * D_OUT + lane]);
    __syncthreads();

    // each warp computes 4 node-rows (both batches)
#pragma unroll
    for (int j = 0; j < 4; ++j) {
        const int row = warp * 4 + j;
        float acc0 = 0.f, acc1 = 0.f;
#pragma unroll
        for (int d4 = 0; d4 < D_IN / 4; ++d4) {
            const float4 a = xs[0][row][d4];   // uniform LDS.128 broadcast
            const float4 b = xs[1][row][d4];
            acc0 = fmaf(a.x, w[d4 * 4 + 0], acc0);
            acc1 = fmaf(b.x, w[d4 * 4 + 0], acc1);
            acc0 = fmaf(a.y, w[d4 * 4 + 1], acc0);
            acc1 = fmaf(b.y, w[d4 * 4 + 1], acc1);
            acc0 = fmaf(a.z, w[d4 * 4 + 2], acc0);
            acc1 = fmaf(b.z, w[d4 * 4 + 2], acc1);
            acc0 = fmaf(a.w, w[d4 * 4 + 3], acc0);
            acc1 = fmaf(b.w, w[d4 * 4 + 3], acc1);
        }
        const int r = rBase + row;
        if (!isW0)
            g_hkA[r * D_OUT + lane] = __floats2half2_rn(acc0, acc1);
        else
            g_h0 [r * D_OUT + lane] = make_float2(acc0 * ALPHA_F, acc1 * ALPHA_F);
    }
}

// ---------------- 2) fused CSR-build + INLINE first SpMM iterate --------------
// Gathers for iterate 1 happen AT nnz discovery, hidden under the DRAM scan.
__global__ void csr_spmm1_kernel(const float* __restrict__ adj) {
    __shared__ float shs[8][32];
    __shared__ float shq[8][32];

    const int warp = threadIdx.x >> 5;
    const int lane = threadIdx.x & 31;
    const int r    = blockIdx.x * 8 + warp;

    const float4* row = (const float4*)(adj + (size_t)r * N_NODES);
    int2* out = (int2*)&g_cv4[(size_t)r * (MAX_NNZ / 2)];
    const __half2* __restrict__ src = g_hkA;

    const float2 h0 = __ldg(&g_h0[r * D_OUT + lane]);
    float acc0 = h0.x, acc1 = h0.y;
    int base = 0;

    for (int ch = 0; ch < N_NODES / 128; ch += 2) {
        float4 vA = __ldcs(&row[ch * 32 + lane]);
        float4 vB = __ldcs(&row[(ch + 1) * 32 + lane]);
#pragma unroll
        for (int half = 0; half < 2; ++half) {
            const float4 v = half ? vB : vA;
            const bool any = (v.x != 0.f) | (v.y != 0.f) | (v.z != 0.f) | (v.w != 0.f);
            const unsigned am = __ballot_sync(0xffffffffu, any);
            if (am == 0u) continue;                 // uniform branch
            const float e[4] = {v.x, v.y, v.z, v.w};
#pragma unroll
            for (int k = 0; k < 4; ++k) {
                const bool nz = (e[k] != 0.0f);
                const unsigned m = __ballot_sync(0xffffffffu, nz);
                if (nz) {
                    int pos = base + __popc(m & ((1u << lane) - 1u));
                    if (pos < MAX_NNZ)
                        out[pos] = make_int2(((ch + half) * 128 + lane * 4 + k) << 5,
                                             __float_as_int(e[k] * OMA_F));
                }
                base += __popc(m);

                // inline iterate-1 gather for each discovered nnz
                unsigned mm = m;
                const int colbase32 = (((ch + half) * 128 + k) << 5) + lane;
                while (mm) {
                    const int j = __ffs(mm) - 1;
                    mm &= mm - 1;
                    const float vv = __shfl_sync(0xffffffffu, e[k], j) * OMA_F;
                    const __half2 g = __ldg(&src[colbase32 + (j << 7)]);
                    const float2 f = __half22float2(g);
                    acc0 = fmaf(vv, f.x, acc0);
                    acc1 = fmaf(vv, f.y, acc1);
                }
            }
        }
    }
    int cnt  = base < MAX_NNZ ? base : MAX_NNZ;
    int cntp = (cnt + 7) & ~7;
    for (int j = cnt + lane; j < cntp; j += 32)
        out[j] = make_int2(0, 0);                    // val = 0 padding
    if (lane == 0) g_cnt[r] = cntp;

    // ---- iterate-1 epilogue ----
    g_hkB[r * D_OUT + lane] = __floats2half2_rn(acc0, acc1);
    g_y[(size_t)r * C_CH + lane]             = acc0;
    g_y[(size_t)(N_NODES + r) * C_CH + lane] = acc1;

    shs[warp][lane] = acc0 + acc1;
    shq[warp][lane] = fmaf(acc0, acc0, acc1 * acc1);
    __syncthreads();
    if (warp == 0) {
        float s = 0.f;
#pragma unroll
        for (int w = 0; w < 8; ++w) s += shs[w][lane];
        g_psum[blockIdx.x * D_OUT + lane] = s;
    }
    if (warp == 1) {
        float q = 0.f;
#pragma unroll
        for (int w = 0; w < 8; ++w) q += shq[w][lane];
        g_psq[blockIdx.x * D_OUT + lane] = q;
    }
}

// ---------------- 3) persistent: iterates 2-4 + BN + norm + ReLU -------------
__global__ void __launch_bounds__(256, 8)
post_kernel(const float* __restrict__ gamma,
            const float* __restrict__ beta,
            float* __restrict__ out) {
    __shared__ int4  meta[8][MAX_NNZ / 2];     // 8 KB
    __shared__ float shs[8][32];
    __shared__ float shq[8][32];

    const int warp = threadIdx.x >> 5;
    const int lane = threadIdx.x & 31;
    const int r    = blockIdx.x * 8 + warp;

    // stage metadata ONCE for all 3 iterates
    const int4* __restrict__ cv = g_cv4 + (size_t)r * (MAX_NNZ / 2);
    meta[warp][lane]      = __ldg(&cv[lane]);
    meta[warp][lane + 32] = __ldg(&cv[lane + 32]);
    const int nIt = g_cnt[r] >> 2;             // groups of 4 nnz
    const float2 h0 = __ldg(&g_h0[r * D_OUT + lane]);
    __syncwarp();

    for (int k = 1; k < 4; ++k) {
        const __half2* __restrict__ src = (k & 1) ? g_hkB : g_hkA;
        __half2* __restrict__ dst       = (k & 1) ? g_hkA : g_hkB;

        float acc0 = h0.x, acc1 = h0.y;
#pragma unroll 2
        for (int it = 0; it < nIt; ++it) {
            const int4 a = meta[warp][it * 2 + 0];   // uniform LDS.128
            const int4 b = meta[warp][it * 2 + 1];

            const __half2 g0 = __ldg(&src[a.x + lane]);
            const __half2 g1 = __ldg(&src[a.z + lane]);
            const __half2 g2 = __ldg(&src[b.x + lane]);
            const __half2 g3 = __ldg(&src[b.z + lane]);

            float2 f;
            f = __half22float2(g0); acc0 = fmaf(__int_as_float(a.y), f.x, acc0); acc1 = fmaf(__int_as_float(a.y), f.y, acc1);
            f = __half22float2(g1); acc0 = fmaf(__int_as_float(a.w), f.x, acc0); acc1 = fmaf(__int_as_float(a.w), f.y, acc1);
            f = __half22float2(g2); acc0 = fmaf(__int_as_float(b.y), f.x, acc0); acc1 = fmaf(__int_as_float(b.y), f.y, acc1);
            f = __half22float2(g3); acc0 = fmaf(__int_as_float(b.w), f.x, acc0); acc1 = fmaf(__int_as_float(b.w), f.y, acc1);
        }

        if (k < 3)
            dst[r * D_OUT + lane] = __floats2half2_rn(acc0, acc1);
        g_y[(size_t)r * C_CH + k * D_OUT + lane]             = acc0;
        g_y[(size_t)(N_NODES + r) * C_CH + k * D_OUT + lane] = acc1;

        shs[warp][lane] = acc0 + acc1;
        shq[warp][lane] = fmaf(acc0, acc0, acc1 * acc1);
        __syncthreads();
        if (warp == 0) {
            float s = 0.f;
#pragma unroll
            for (int w = 0; w < 8; ++w) s += shs[w][lane];
            g_psum[(k * NBLK + blockIdx.x) * D_OUT + lane] = s;
        }
        if (warp == 1) {
            float q = 0.f;
#pragma unroll
            for (int w = 0; w < 8; ++w) q += shq[w][lane];
            g_psq[(k * NBLK + blockIdx.x) * D_OUT + lane] = q;
        }
        grid_sync();                           // hk + partials visible everywhere
    }

    // ---- BN finalize: block c (c < 128) owns channel c ----
    if (blockIdx.x < C_CH) {
        const int c     = blockIdx.x;
        const int slice = c >> 5;
        const int ln    = c & 31;
        const int t     = threadIdx.x;
        float s = 0.f, q = 0.f;
        for (int j = t; j < NBLK; j += 256) {
            s += g_psum[(slice * NBLK + j) * D_OUT + ln];
            q += g_psq [(slice * NBLK + j) * D_OUT + ln];
        }
        float* fs = &shs[0][0];
        float* fq = &shq[0][0];
        fs[t] = s; fq[t] = q;
        __syncthreads();
        if (t < 128) { fs[t] += fs[t + 128]; fq[t] += fq[t + 128]; }
        __syncthreads();
        if (t < 64)  { fs[t] += fs[t + 64];  fq[t] += fq[t + 64];  }
        __syncthreads();
        if (t < 32) {
            s = fs[t] + fs[t + 32];
            q = fq[t] + fq[t + 32];
#pragma unroll
            for (int off = 16; off > 0; off >>= 1) {
                s += __shfl_down_sync(0xffffffffu, s, off);
                q += __shfl_down_sync(0xffffffffu, q, off);
            }
            if (t == 0) {
                const float inv  = 1.0f / (float)NSAMP;
                const float mean = s * inv;
                const float var  = q * inv - mean * mean;
                const float sc   = gamma[c] * rsqrtf(var + BN_EPS_F);
                g_scale[c] = sc;
                g_shift[c] = beta[c] - mean * sc;
            }
        }
    }
    grid_sync();                               // scale/shift visible everywhere

    // ---- normalize + ReLU: 512 float4 per block ----
    const float4* yv = (const float4*)g_y;
    float4*       ov = (float4*)out;
#pragma unroll
    for (int i = 0; i < 2; ++i) {
        const int idx = blockIdx.x * 512 + i * 256 + threadIdx.x;
        float4 v = yv[idx];
        const int c0 = (idx & 31) * 4;
        v.x = fmaxf(0.f, fmaf(v.x, g_scale[c0 + 0], g_shift[c0 + 0]));
        v.y = fmaxf(0.f, fmaf(v.y, g_scale[c0 + 1], g_shift[c0 + 1]));
        v.z = fmaxf(0.f, fmaf(v.z, g_scale[c0 + 2], g_shift[c0 + 2]));
        v.w = fmaxf(0.f, fmaf(v.w, g_scale[c0 + 3], g_shift[c0 + 3]));
        ov[idx] = v;
    }
}

// ---------------- launch ----------------
extern "C" void kernel_launch(void* const* d_in, const int* in_sizes, int n_in,
                              void* d_out, int out_size) {
    const float* x     = (const float*)d_in[0];
    const float* x0    = (const float*)d_in[1];
    const float* adj   = (const float*)d_in[2];
    const float* W     = (const float*)d_in[3];
    const float* W0    = (const float*)d_in[4];
    const float* gamma = (const float*)d_in[5];
    const float* beta  = (const float*)d_in[6];
    float* out = (float*)d_out;

    gemm_kernel<<<2048, 64>>>(x, x0, W, W0);
    csr_spmm1_kernel<<<N_NODES / 8, 256>>>(adj);     // scan + inline iterate 1
    post_kernel<<<NBLK, 256>>>(gamma, beta, out);    // iterates 2-4 + BN + norm
}